// round 6
// baseline (speedup 1.0000x reference)
#include <cuda_runtime.h>
#include <cstdint>

// DySepConvAtten v6: mma.sync tf32 (base PTX ISA) for both GEMMs.
// B=512, N=100, C=256, K=3, J=103. One CTA per batch, 512 threads.
#define NROW 100
#define CDIM 256
#define JDIM 103
#define NTHR 512

// float offsets in dynamic smem
#define O_SA   0        // phaseA A-frag [7][16][128]=14336 | later dyBuf [112][104]=11648
#define O_SB   14336    // phaseA B-frag [13][16][64]=13312 | later pwFrag [7][13][128]=11648
#define O_BC   27648    // phaseC B-frag [32][13][64]=26624
#define O_BIAS 54272    // 104 (pad 112)
#define O_PS   54384    // psum [4][128]
#define O_PQ   54896    // pssq [4][128]
#define O_MU   55408    // 128
#define O_INV  55536    // 128
#define O_G    55664    // 256
#define O_BT   55920    // 256
#define SMEMF  56176    // 224,704 bytes

static __device__ __forceinline__ uint32_t tf32c(float f) {
    uint32_t u;
    asm("cvt.rna.tf32.f32 %0, %1;" : "=r"(u) : "f"(f));
    return u;
}
static __device__ __forceinline__ void mma8(float* d, uint4 a, uint2 b) {
    asm volatile(
        "mma.sync.aligned.m16n8k8.row.col.f32.tf32.tf32.f32 "
        "{%0,%1,%2,%3}, {%4,%5,%6,%7}, {%8,%9}, {%0,%1,%2,%3};"
        : "+f"(d[0]), "+f"(d[1]), "+f"(d[2]), "+f"(d[3])
        : "r"(a.x), "r"(a.y), "r"(a.z), "r"(a.w), "r"(b.x), "r"(b.y));
}

__global__ void __launch_bounds__(NTHR, 1)
dysep_kernel(const float* __restrict__ query, const float* __restrict__ value,
             const float* __restrict__ Wwl,   const float* __restrict__ bwl,
             const float* __restrict__ gamma, const float* __restrict__ beta,
             float* __restrict__ out)
{
    extern __shared__ float sm[];
    const int b    = blockIdx.x;
    const int tid  = threadIdx.x;
    const int w    = tid >> 5;
    const int lane = tid & 31;

    const float* qg = query + (size_t)b * (NROW * CDIM);
    const float* vg = value + (size_t)b * (NROW * CDIM);
    float*       og = out   + (size_t)b * (NROW * CDIM);

    // ---- stage bias / gamma / beta ----
    if (tid < 112) sm[O_BIAS + tid] = (tid < JDIM) ? bwl[tid] : 0.0f;
    if (tid < 256) { sm[O_G + tid] = gamma[tid]; sm[O_BT + tid] = beta[tid]; }

    // ================= Phase A: dy = Q @ W + b  (2 K-chunks of 128) =================
    // job (w<14): mt = w>>1 (rows mt*16..+15), n-tiles nt0..nt0+ntn-1
    const int mtA = w >> 1;
    const int nt0 = (w & 1) ? 7 : 0;
    const int ntn = (w & 1) ? 6 : 7;
    float dA[7][4];
    #pragma unroll
    for (int t = 0; t < 7; ++t)
        #pragma unroll
        for (int r = 0; r < 4; ++r) dA[t][r] = 0.0f;

    #pragma unroll 1
    for (int ch = 0; ch < 2; ++ch) {
        const int c0 = ch << 7;
        __syncthreads();   // protect SA/SB from previous chunk's readers
        // A-frag: Q[n][c0..c0+127], fragment order, tf32-rounded
        for (int idx = tid; idx < NROW * 32; idx += NTHR) {
            const int n = idx >> 5, c4 = (idx & 31) << 2;
            const float4 v = *(const float4*)(qg + n * CDIM + c0 + c4);
            const int mt = n >> 4, m = n & 15;
            const int kt = c4 >> 3, cc = c4 & 7;
            uint32_t* p = (uint32_t*)(sm + O_SA + (mt * 16 + kt) * 128
                                      + (m & 7) * 16 + ((m >> 3) + ((cc >> 2) << 1)));
            p[0] = tf32c(v.x); p[4] = tf32c(v.y); p[8] = tf32c(v.z); p[12] = tf32c(v.w);
        }
        for (int idx = tid; idx < 12 * 128; idx += NTHR) {   // zero pad rows 100..111
            const int n = 100 + (idx >> 7), cl = idx & 127;
            const int mt = n >> 4, m = n & 15, kt = cl >> 3, cc = cl & 7;
            sm[O_SA + (mt * 16 + kt) * 128 + ((m & 7) * 4 + (cc & 3)) * 4
               + ((m >> 3) + ((cc >> 2) << 1))] = 0.0f;
        }
        // B-frag: W[c0+ck][j]
        for (int idx = tid; idx < 128 * JDIM; idx += NTHR) {
            const int ck = idx / JDIM;
            const int j  = idx - ck * JDIM;
            const float v = Wwl[(c0 + ck) * JDIM + j];
            const int nt = j >> 3, jn = j & 7, kt = ck >> 3, kk = ck & 7;
            sm[O_SB + (nt * 16 + kt) * 64 + (jn * 4 + (kk & 3)) * 2 + (kk >> 2)]
                = __uint_as_float(tf32c(v));
        }
        for (int idx = tid; idx < 128; idx += NTHR) {        // zero pad col j=103
            const int kt = idx >> 3, kk = idx & 7;
            sm[O_SB + (12 * 16 + kt) * 64 + (28 + (kk & 3)) * 2 + (kk >> 2)] = 0.0f;
        }
        __syncthreads();

        if (w < 14) {
            #pragma unroll
            for (int kt = 0; kt < 16; ++kt) {
                const uint4 a = *(const uint4*)(sm + O_SA + (mtA * 16 + kt) * 128 + lane * 4);
                #pragma unroll 7
                for (int t = 0; t < ntn; ++t) {
                    const uint2 bb = *(const uint2*)(sm + O_SB + ((nt0 + t) * 16 + kt) * 64 + lane * 2);
                    mma8(dA[t], a, bb);
                }
            }
        }
    }
    __syncthreads();   // mma reads done; O_SA becomes dyBuf

    // ---- Epilogue A: dy = D + bias -> dyBuf[112][104] ----
    if (w < 14) {
        const int row0 = mtA * 16 + (lane >> 2);
        #pragma unroll 7
        for (int t = 0; t < ntn; ++t) {
            const int j0 = (nt0 + t) * 8 + 2 * (lane & 3);
            const float b0 = sm[O_BIAS + j0], b1 = sm[O_BIAS + j0 + 1];
            *(float2*)(sm + O_SA + row0 * 104 + j0)       = make_float2(dA[t][0] + b0, dA[t][1] + b1);
            *(float2*)(sm + O_SA + (row0 + 8) * 104 + j0) = make_float2(dA[t][2] + b0, dA[t][3] + b1);
        }
    }
    __syncthreads();

    // ---- pwFrag staging (A' for phase C): pw[n][m] = dy[n][3+m], m>=101 -> 0 ----
    for (int fid = tid; fid < 7 * 13 * 32; fid += NTHR) {
        const int mt = fid / 416;
        const int rem = fid - mt * 416;
        const int kt = rem >> 5;
        const int ln = rem & 31;
        const int r0 = mt * 16 + (ln >> 2);
        const int c  = kt * 8 + (ln & 3);     // m index, <= 99 for a0/a1
        const float a0 = sm[O_SA + r0 * 104 + 3 + c];
        const float a1 = sm[O_SA + (r0 + 8) * 104 + 3 + c];
        const float a2 = (c <= 96) ? sm[O_SA + r0 * 104 + 7 + c] : 0.0f;
        const float a3 = (c <= 96) ? sm[O_SA + (r0 + 8) * 104 + 7 + c] : 0.0f;
        const uint4 u = make_uint4(tf32c(a0), tf32c(a1), tf32c(a2), tf32c(a3));
        *(uint4*)(sm + O_SB + (mt * 13 + kt) * 128 + ln * 4) = u;
    }

    // ---- Phase B: depth = relu(conv(value)) -> B'-frag (k=m, n=c) ----
    for (int idx = tid; idx < NROW * 64; idx += NTHR) {
        const int m = idx >> 6;
        const int c4 = (idx & 63) << 2;
        const float* vr = vg + m * CDIM;
        const float d0 = sm[O_SA + m * 104 + 0];
        const float d1 = sm[O_SA + m * 104 + 1];
        const float d2 = sm[O_SA + m * 104 + 2];
        const float4 vc = *(const float4*)(vr + c4);
        const float vl  = (c4 == 0)        ? 0.0f : vr[c4 - 1];
        const float vrt = (c4 == CDIM - 4) ? 0.0f : vr[c4 + 4];
        float o[4];
        o[0] = fmaxf(fmaf(d0, vl,   fmaf(d1, vc.x, d2 * vc.y)), 0.0f);
        o[1] = fmaxf(fmaf(d0, vc.x, fmaf(d1, vc.y, d2 * vc.z)), 0.0f);
        o[2] = fmaxf(fmaf(d0, vc.y, fmaf(d1, vc.z, d2 * vc.w)), 0.0f);
        o[3] = fmaxf(fmaf(d0, vc.z, fmaf(d1, vc.w, d2 * vrt)), 0.0f);
        const int kt = m >> 3, rr = (m & 7) >> 2, mm = m & 3;
        #pragma unroll
        for (int i = 0; i < 4; ++i) {
            const int c = c4 + i;
            sm[O_BC + ((c >> 3) * 13 + kt) * 64 + ((c & 7) * 4 + mm) * 2 + rr]
                = __uint_as_float(tf32c(o[i]));
        }
    }
    for (int idx = tid; idx < 4 * CDIM; idx += NTHR) {   // zero depth pad rows m=100..103
        const int m = 100 + (idx >> 8);
        const int c = idx & 255;
        sm[O_BC + ((c >> 3) * 13 + 12) * 64 + ((c & 7) * 4 + (m & 3)) * 2 + 1] = 0.0f;
    }
    __syncthreads();

    // ================= Phase C: out = pw @ depth  (K=104, 13 ksteps) =================
    // jobs: jid = w (+16); mt = jid>>2, nb = jid&3 (cols nb*64..+63)
    float dC[2][8][4];
    #pragma unroll
    for (int jj = 0; jj < 2; ++jj)
        #pragma unroll
        for (int t = 0; t < 8; ++t)
            #pragma unroll
            for (int r = 0; r < 4; ++r) dC[jj][t][r] = 0.0f;

    const int njob = (w < 12) ? 2 : 1;
    #pragma unroll
    for (int jj = 0; jj < 2; ++jj) {
        if (jj >= njob) break;
        const int jid = w + jj * 16;
        const int mt = jid >> 2, nbt0 = (jid & 3) * 8;
        #pragma unroll
        for (int kt = 0; kt < 13; ++kt) {
            const uint4 a = *(const uint4*)(sm + O_SB + (mt * 13 + kt) * 128 + lane * 4);
            #pragma unroll
            for (int t = 0; t < 8; ++t) {
                const uint2 bb = *(const uint2*)(sm + O_BC + ((nbt0 + t) * 13 + kt) * 64 + lane * 2);
                mma8(dC[jj][t], a, bb);
            }
        }
    }

    // ---- LN partial sums ----
    #pragma unroll
    for (int jj = 0; jj < 2; ++jj) {
        if (jj >= njob) break;
        const int jid = w + jj * 16;
        const int mt = jid >> 2, nb = jid & 3;
        float s0 = 0, q0 = 0, s1 = 0, q1 = 0;
        #pragma unroll
        for (int t = 0; t < 8; ++t) {
            s0 += dC[jj][t][0] + dC[jj][t][1];
            q0 = fmaf(dC[jj][t][0], dC[jj][t][0], fmaf(dC[jj][t][1], dC[jj][t][1], q0));
            s1 += dC[jj][t][2] + dC[jj][t][3];
            q1 = fmaf(dC[jj][t][2], dC[jj][t][2], fmaf(dC[jj][t][3], dC[jj][t][3], q1));
        }
        s0 += __shfl_xor_sync(~0u, s0, 1); s0 += __shfl_xor_sync(~0u, s0, 2);
        q0 += __shfl_xor_sync(~0u, q0, 1); q0 += __shfl_xor_sync(~0u, q0, 2);
        s1 += __shfl_xor_sync(~0u, s1, 1); s1 += __shfl_xor_sync(~0u, s1, 2);
        q1 += __shfl_xor_sync(~0u, q1, 1); q1 += __shfl_xor_sync(~0u, q1, 2);
        if ((lane & 3) == 0) {
            const int row0 = mt * 16 + (lane >> 2);
            sm[O_PS + nb * 128 + row0]     = s0;
            sm[O_PQ + nb * 128 + row0]     = q0;
            sm[O_PS + nb * 128 + row0 + 8] = s1;
            sm[O_PQ + nb * 128 + row0 + 8] = q1;
        }
    }
    __syncthreads();

    if (tid < 112) {
        float S  = sm[O_PS + tid] + sm[O_PS + 128 + tid] + sm[O_PS + 256 + tid] + sm[O_PS + 384 + tid];
        float SS = sm[O_PQ + tid] + sm[O_PQ + 128 + tid] + sm[O_PQ + 256 + tid] + sm[O_PQ + 384 + tid];
        const float mu = S * (1.0f / 256.0f);
        float var = fmaf(-mu, mu, SS * (1.0f / 256.0f));
        var = fmaxf(var, 0.0f);
        sm[O_MU + tid]  = mu;
        sm[O_INV + tid] = rsqrtf(var + 1e-5f);
    }
    __syncthreads();

    // ---- normalize + store ----
    #pragma unroll
    for (int jj = 0; jj < 2; ++jj) {
        if (jj >= njob) break;
        const int jid = w + jj * 16;
        const int mt = jid >> 2, nbt0 = (jid & 3) * 8;
        const int row0 = mt * 16 + (lane >> 2);
        const float mu0 = sm[O_MU + row0],     iv0 = sm[O_INV + row0];
        const float mu1 = sm[O_MU + row0 + 8], iv1 = sm[O_INV + row0 + 8];
        #pragma unroll
        for (int t = 0; t < 8; ++t) {
            const int j0 = (nbt0 + t) * 8 + 2 * (lane & 3);
            const float g0 = sm[O_G + j0], g1 = sm[O_G + j0 + 1];
            const float e0 = sm[O_BT + j0], e1 = sm[O_BT + j0 + 1];
            if (row0 < NROW)
                *(float2*)(og + row0 * CDIM + j0) = make_float2(
                    fmaf((dC[jj][t][0] - mu0) * iv0, g0, e0),
                    fmaf((dC[jj][t][1] - mu0) * iv0, g1, e1));
            if (row0 + 8 < NROW)
                *(float2*)(og + (row0 + 8) * CDIM + j0) = make_float2(
                    fmaf((dC[jj][t][2] - mu1) * iv1, g0, e0),
                    fmaf((dC[jj][t][3] - mu1) * iv1, g1, e1));
        }
    }
}

extern "C" void kernel_launch(void* const* d_in, const int* in_sizes, int n_in,
                              void* d_out, int out_size)
{
    const float* query = (const float*)d_in[0];
    const float* value = (const float*)d_in[1];
    const float* Wwl   = (const float*)d_in[2];
    const float* bwl   = (const float*)d_in[3];
    const float* gamma = (const float*)d_in[4];
    const float* beta  = (const float*)d_in[5];
    float* out = (float*)d_out;

    const int B = in_sizes[0] / (NROW * CDIM);   // 512
    const size_t smem = SMEMF * sizeof(float);   // 224,704 B
    cudaFuncSetAttribute(dysep_kernel,
                         cudaFuncAttributeMaxDynamicSharedMemorySize, (int)smem);
    dysep_kernel<<<B, NTHR, smem>>>(query, value, Wwl, bwl, gamma, beta, out);
}

// round 9
// speedup vs baseline: 1.1895x; 1.1895x over previous
#include <cuda_runtime.h>
#include <cstdint>

// DySepConvAtten v8: mma.sync tf32, direct conflict-free fragment gathers
// from linear smem buffers. (v7 + sQ stride fix 132->260.)
// B=512, N=100, C=256, K=3, J=103. One CTA per batch, 512 threads.
#define NROW 100
#define CDIM 256
#define JDIM 103
#define NTHR 512

// float offsets / strides in dynamic smem
#define O_SQ   0        // sQ [100][260] = 26000      (stride 260, mod32=4)
#define SQS    260
#define O_DY   0        // dyBuf [112][108] = 12096 (overlays sQ; stride 108, mod32=12)
#define DYS    108
#define O_SW   26000    // sW [256][104] = 26624      (stride 104, mod32=8)
#define SWS    104
#define O_DP   26000    // depthBuf [104][264] = 27456 (overlays sW; stride 264, mod32=8)
#define DPS    264
#define O_BIAS 53456    // 112
#define O_PS   53568    // [4][128]
#define O_PQ   54080    // [4][128]
#define O_MU   54592    // 128
#define O_INV  54720    // 128
#define O_G    54848    // 256
#define O_BT   55104    // 256
#define SMEMF  55360    // 221,440 bytes

static __device__ __forceinline__ uint32_t tf32c(float f) {
    uint32_t u;
    asm("cvt.rna.tf32.f32 %0, %1;" : "=r"(u) : "f"(f));
    return u;
}
static __device__ __forceinline__ void mma8(float* d, uint4 a, uint2 b) {
    asm volatile(
        "mma.sync.aligned.m16n8k8.row.col.f32.tf32.tf32.f32 "
        "{%0,%1,%2,%3}, {%4,%5,%6,%7}, {%8,%9}, {%0,%1,%2,%3};"
        : "+f"(d[0]), "+f"(d[1]), "+f"(d[2]), "+f"(d[3])
        : "r"(a.x), "r"(a.y), "r"(a.z), "r"(a.w), "r"(b.x), "r"(b.y));
}

__global__ void __launch_bounds__(NTHR, 1)
dysep_kernel(const float* __restrict__ query, const float* __restrict__ value,
             const float* __restrict__ Wwl,   const float* __restrict__ bwl,
             const float* __restrict__ gamma, const float* __restrict__ beta,
             float* __restrict__ out)
{
    extern __shared__ float sm[];
    const uint32_t* smu = (const uint32_t*)sm;
    const int b    = blockIdx.x;
    const int tid  = threadIdx.x;
    const int w    = tid >> 5;
    const int lane = tid & 31;
    const int lg   = lane >> 2;     // group id 0..7
    const int lt   = lane & 3;      // tid-in-group 0..3

    const float* qg = query + (size_t)b * (NROW * CDIM);
    const float* vg = value + (size_t)b * (NROW * CDIM);
    float*       og = out   + (size_t)b * (NROW * CDIM);

    // ---- stage bias / gamma / beta ----
    if (tid < 112) sm[O_BIAS + tid] = (tid < JDIM) ? bwl[tid] : 0.0f;
    if (tid < 256) { sm[O_G + tid] = gamma[tid]; sm[O_BT + tid] = beta[tid]; }

    // ---- stage sQ (tf32-rounded, coalesced float4; stride 260) ----
    for (int idx = tid; idx < NROW * 64; idx += NTHR) {
        const int n = idx >> 6, c4 = (idx & 63) << 2;
        const float4 v = *(const float4*)(qg + n * CDIM + c4);
        uint4 u;
        u.x = tf32c(v.x); u.y = tf32c(v.y); u.z = tf32c(v.z); u.w = tf32c(v.w);
        *(uint4*)(sm + O_SQ + n * SQS + c4) = u;
    }
    // ---- stage sW[c][j] (linear, stride 104, j=103 zero) ----
    for (int idx = tid; idx < 256 * 104; idx += NTHR) {
        const int c = (int)(((unsigned)idx * 40330u) >> 22);   // idx/104 (exact for idx<26624)
        const int j = idx - c * 104;
        const float v = (j < JDIM) ? Wwl[c * JDIM + j] : 0.0f;
        sm[O_SW + idx] = __uint_as_float(tf32c(v));
    }
    __syncthreads();

    // ================= Phase A: dy = Q @ W  (K=256, 32 ksteps) =================
    // job (w<14): mt = w>>1 (rows mt*16..+15); n-tiles nt0..nt0+ntn-1 (13 total)
    const int mtA = w >> 1;
    const int nt0 = (w & 1) ? 7 : 0;
    const int ntn = (w & 1) ? 6 : 7;
    float dA[7][4];
    #pragma unroll
    for (int t = 0; t < 7; ++t)
        #pragma unroll
        for (int r = 0; r < 4; ++r) dA[t][r] = 0.0f;

    if (w < 14) {
        const int r0 = mtA * 16 + lg;
        const uint32_t* qa = smu + O_SQ + r0 * SQS + lt;
        const uint32_t* qb = qa + 8 * SQS;
        const uint32_t* bp = smu + O_SW + lt * SWS + lg + nt0 * 8;
        #pragma unroll 8
        for (int kt = 0; kt < 32; ++kt) {
            const int kc = kt * 8;
            uint4 a;
            a.x = qa[kc]; a.y = qb[kc]; a.z = qa[kc + 4]; a.w = qb[kc + 4];
            const uint32_t* bk = bp + kc * SWS;
            #pragma unroll 7
            for (int t = 0; t < ntn; ++t) {
                uint2 bb;
                bb.x = bk[t * 8];
                bb.y = bk[4 * SWS + t * 8];
                mma8(dA[t], a, bb);
            }
        }
    }
    __syncthreads();   // phase-A smem reads done; sQ region becomes dyBuf

    // ---- Epilogue A: dy = D + bias -> dyBuf (tf32-rounded) ----
    if (w < 14) {
        const int r0 = mtA * 16 + lg;
        #pragma unroll 7
        for (int t = 0; t < ntn; ++t) {
            const int j0 = (nt0 + t) * 8 + 2 * lt;
            const float b0 = sm[O_BIAS + j0], b1 = sm[O_BIAS + j0 + 1];
            if (r0 < NROW) {
                float2 v = make_float2(__uint_as_float(tf32c(dA[t][0] + b0)),
                                       __uint_as_float(tf32c(dA[t][1] + b1)));
                *(float2*)(sm + O_DY + r0 * DYS + j0) = v;
            }
            if (r0 + 8 < NROW) {
                float2 v = make_float2(__uint_as_float(tf32c(dA[t][2] + b0)),
                                       __uint_as_float(tf32c(dA[t][3] + b1)));
                *(float2*)(sm + O_DY + (r0 + 8) * DYS + j0) = v;
            }
        }
    }
    // zero dyBuf cols 103..106 (pw K-padding), rows 0..99
    for (int idx = tid; idx < 400; idx += NTHR)
        sm[O_DY + (idx >> 2) * DYS + 103 + (idx & 3)] = 0.0f;
    // zero dyBuf pad rows 100..111 (read as pw A-operand for discarded rows)
    for (int idx = tid; idx < 12 * DYS; idx += NTHR)
        sm[O_DY + 100 * DYS + idx] = 0.0f;
    __syncthreads();

    // ================= Phase B: depth = relu(conv(value)) -> depthBuf ===========
    for (int idx = tid; idx < NROW * 64; idx += NTHR) {
        const int m = idx >> 6;
        const int c4 = (idx & 63) << 2;
        const float* vr = vg + m * CDIM;
        const float d0 = sm[O_DY + m * DYS + 0];
        const float d1 = sm[O_DY + m * DYS + 1];
        const float d2 = sm[O_DY + m * DYS + 2];
        const float4 vc = *(const float4*)(vr + c4);
        const float vl  = (c4 == 0)        ? 0.0f : vr[c4 - 1];
        const float vrt = (c4 == CDIM - 4) ? 0.0f : vr[c4 + 4];
        uint4 u;
        u.x = tf32c(fmaxf(fmaf(d0, vl,   fmaf(d1, vc.x, d2 * vc.y)), 0.0f));
        u.y = tf32c(fmaxf(fmaf(d0, vc.x, fmaf(d1, vc.y, d2 * vc.z)), 0.0f));
        u.z = tf32c(fmaxf(fmaf(d0, vc.y, fmaf(d1, vc.z, d2 * vc.w)), 0.0f));
        u.w = tf32c(fmaxf(fmaf(d0, vc.z, fmaf(d1, vc.w, d2 * vrt)), 0.0f));
        *(uint4*)(sm + O_DP + m * DPS + c4) = u;
    }
    // zero depth pad rows m=100..103
    for (int idx = tid; idx < 4 * 256; idx += NTHR)
        sm[O_DP + (100 + (idx >> 8)) * DPS + (idx & 255)] = 0.0f;
    __syncthreads();

    // ================= Phase C: out = pw @ depth  (K=104, 13 ksteps) ============
    // jobs jid = w, w+16 (jid<28): mt = jid>>2 (rows), nb = jid&3 (cols nb*64..+63)
    float dC[2][8][4];
    #pragma unroll
    for (int jj = 0; jj < 2; ++jj)
        #pragma unroll
        for (int t = 0; t < 8; ++t)
            #pragma unroll
            for (int r = 0; r < 4; ++r) dC[jj][t][r] = 0.0f;

    const int njob = (w < 12) ? 2 : 1;
    #pragma unroll
    for (int jj = 0; jj < 2; ++jj) {
        if (jj >= njob) break;
        const int jid = w + jj * 16;
        const int mt = jid >> 2, nb = jid & 3;
        const int r0 = mt * 16 + lg;
        const uint32_t* pa = smu + O_DY + r0 * DYS + 3 + lt;
        const uint32_t* pb = pa + 8 * DYS;
        const uint32_t* dp = smu + O_DP + lt * DPS + nb * 64 + lg;
        #pragma unroll
        for (int kt = 0; kt < 13; ++kt) {
            const int kc = kt * 8;
            uint4 a;
            a.x = pa[kc]; a.y = pb[kc]; a.z = pa[kc + 4]; a.w = pb[kc + 4];
            const uint32_t* dk = dp + kc * DPS;
            #pragma unroll
            for (int t = 0; t < 8; ++t) {
                uint2 bb;
                bb.x = dk[t * 8];
                bb.y = dk[4 * DPS + t * 8];
                mma8(dC[jj][t], a, bb);
            }
        }
    }

    // ---- LN partial sums ----
    #pragma unroll
    for (int jj = 0; jj < 2; ++jj) {
        if (jj >= njob) break;
        const int jid = w + jj * 16;
        const int mt = jid >> 2, nb = jid & 3;
        float s0 = 0, q0 = 0, s1 = 0, q1 = 0;
        #pragma unroll
        for (int t = 0; t < 8; ++t) {
            s0 += dC[jj][t][0] + dC[jj][t][1];
            q0 = fmaf(dC[jj][t][0], dC[jj][t][0], fmaf(dC[jj][t][1], dC[jj][t][1], q0));
            s1 += dC[jj][t][2] + dC[jj][t][3];
            q1 = fmaf(dC[jj][t][2], dC[jj][t][2], fmaf(dC[jj][t][3], dC[jj][t][3], q1));
        }
        s0 += __shfl_xor_sync(~0u, s0, 1); s0 += __shfl_xor_sync(~0u, s0, 2);
        q0 += __shfl_xor_sync(~0u, q0, 1); q0 += __shfl_xor_sync(~0u, q0, 2);
        s1 += __shfl_xor_sync(~0u, s1, 1); s1 += __shfl_xor_sync(~0u, s1, 2);
        q1 += __shfl_xor_sync(~0u, q1, 1); q1 += __shfl_xor_sync(~0u, q1, 2);
        if (lt == 0) {
            const int row0 = mt * 16 + lg;
            sm[O_PS + nb * 128 + row0]     = s0;
            sm[O_PQ + nb * 128 + row0]     = q0;
            sm[O_PS + nb * 128 + row0 + 8] = s1;
            sm[O_PQ + nb * 128 + row0 + 8] = q1;
        }
    }
    __syncthreads();

    if (tid < 112) {
        const float S  = sm[O_PS + tid] + sm[O_PS + 128 + tid] + sm[O_PS + 256 + tid] + sm[O_PS + 384 + tid];
        const float SS = sm[O_PQ + tid] + sm[O_PQ + 128 + tid] + sm[O_PQ + 256 + tid] + sm[O_PQ + 384 + tid];
        const float mu = S * (1.0f / 256.0f);
        float var = fmaf(-mu, mu, SS * (1.0f / 256.0f));
        var = fmaxf(var, 0.0f);
        sm[O_MU + tid]  = mu;
        sm[O_INV + tid] = rsqrtf(var + 1e-5f);
    }
    __syncthreads();

    // ---- normalize + store ----
    #pragma unroll
    for (int jj = 0; jj < 2; ++jj) {
        if (jj >= njob) break;
        const int jid = w + jj * 16;
        const int mt = jid >> 2, nb = jid & 3;
        const int row0 = mt * 16 + lg;
        const float mu0 = sm[O_MU + row0],     iv0 = sm[O_INV + row0];
        const float mu1 = sm[O_MU + row0 + 8], iv1 = sm[O_INV + row0 + 8];
        #pragma unroll
        for (int t = 0; t < 8; ++t) {
            const int j0 = nb * 64 + t * 8 + 2 * lt;
            const float g0 = sm[O_G + j0], g1 = sm[O_G + j0 + 1];
            const float e0 = sm[O_BT + j0], e1 = sm[O_BT + j0 + 1];
            if (row0 < NROW)
                *(float2*)(og + row0 * CDIM + j0) = make_float2(
                    fmaf((dC[jj][t][0] - mu0) * iv0, g0, e0),
                    fmaf((dC[jj][t][1] - mu0) * iv0, g1, e1));
            if (row0 + 8 < NROW)
                *(float2*)(og + (row0 + 8) * CDIM + j0) = make_float2(
                    fmaf((dC[jj][t][2] - mu1) * iv1, g0, e0),
                    fmaf((dC[jj][t][3] - mu1) * iv1, g1, e1));
        }
    }
}

extern "C" void kernel_launch(void* const* d_in, const int* in_sizes, int n_in,
                              void* d_out, int out_size)
{
    const float* query = (const float*)d_in[0];
    const float* value = (const float*)d_in[1];
    const float* Wwl   = (const float*)d_in[2];
    const float* bwl   = (const float*)d_in[3];
    const float* gamma = (const float*)d_in[4];
    const float* beta  = (const float*)d_in[5];
    float* out = (float*)d_out;

    const int B = in_sizes[0] / (NROW * CDIM);   // 512
    const size_t smem = SMEMF * sizeof(float);   // 221,440 B
    cudaFuncSetAttribute(dysep_kernel,
                         cudaFuncAttributeMaxDynamicSharedMemorySize, (int)smem);
    dysep_kernel<<<B, NTHR, smem>>>(query, value, Wwl, bwl, gamma, beta, out);
}

// round 10
// speedup vs baseline: 2.3111x; 1.9429x over previous
#include <cuda_runtime.h>
#include <cstdint>

// DySepConvAtten v10: two-kernel split, occupancy 2, mma.sync tf32.
// K1: dy = Q@W+b -> pw (shifted, padded) + dw scratch.
// K3: depth = relu(conv) staged in smem; out = pw@depth; fused LN.
#define NROW 100
#define CDIM 256
#define JDIM 103
#define BMAX 512

__device__ float g_pw[BMAX * 104 * 104 + 4096];   // [b][n(104)][m(104)], zero-padded
__device__ float g_dw[BMAX * 100 * 4];            // [b][m][4]

static __device__ __forceinline__ uint32_t tf32c(float f) {
    uint32_t u; asm("cvt.rna.tf32.f32 %0, %1;" : "=r"(u) : "f"(f)); return u;
}
static __device__ __forceinline__ float tf32f(float f) {
    return __uint_as_float(tf32c(f));
}
static __device__ __forceinline__ void mma8(float* d, uint4 a, uint2 b) {
    asm volatile(
        "mma.sync.aligned.m16n8k8.row.col.f32.tf32.tf32.f32 "
        "{%0,%1,%2,%3}, {%4,%5,%6,%7}, {%8,%9}, {%0,%1,%2,%3};"
        : "+f"(d[0]), "+f"(d[1]), "+f"(d[2]), "+f"(d[3])
        : "r"(a.x), "r"(a.y), "r"(a.z), "r"(a.w), "r"(b.x), "r"(b.y));
}

// ================= K1: dy = Q @ W + b =================
// smem: sQc [100][132]=13200f (stride 132, mod32=4) | dyBuf [100][108] overlays
//       sWc [128][104]=13312f at 13200 (stride 104, mod32=8)
//       sBias 104f at 26512 ; total 26616f = 106,464B -> occ 2
#define K1_SW   13200
#define K1_BIAS 26512
#define K1_F    26616
#define SQS 132
#define SWS 104
#define DYS 108

__global__ void __launch_bounds__(256, 2)
k1_gemm(const float* __restrict__ query, const float* __restrict__ Wwl,
        const float* __restrict__ bwl)
{
    extern __shared__ float sm[];
    const uint32_t* smu = (const uint32_t*)sm;
    const int b = blockIdx.x, tid = threadIdx.x;
    const int w = tid >> 5, lane = tid & 31;
    const int lg = lane >> 2, lt = lane & 3;
    const float* qg = query + (size_t)b * (NROW * CDIM);

    if (tid < 104) sm[K1_BIAS + tid] = (tid < JDIM) ? bwl[tid] : 0.0f;

    float dA[13][4];
    #pragma unroll
    for (int t = 0; t < 13; ++t)
        #pragma unroll
        for (int r = 0; r < 4; ++r) dA[t][r] = 0.0f;

    #pragma unroll 1
    for (int ch = 0; ch < 2; ++ch) {
        if (ch) __syncthreads();   // protect prior chunk's smem reads
        // stage Q cols [ch*128 .. +127]
        for (int idx = tid; idx < NROW * 32; idx += 256) {
            const int n = idx >> 5, c4 = (idx & 31) << 2;
            const float4 v = *(const float4*)(qg + n * CDIM + ch * 128 + c4);
            uint4 u;
            u.x = tf32c(v.x); u.y = tf32c(v.y); u.z = tf32c(v.z); u.w = tf32c(v.w);
            *(uint4*)(sm + n * SQS + c4) = u;
        }
        // stage W rows [ch*128 .. +127], cols j (103 + 1 zero pad)
        for (int idx = tid; idx < 128 * 104; idx += 256) {
            const int c = idx / 104;
            const int j = idx - c * 104;
            const float v = (j < JDIM) ? Wwl[(ch * 128 + c) * JDIM + j] : 0.0f;
            sm[K1_SW + idx] = __uint_as_float(tf32c(v));
        }
        __syncthreads();

        if (w < 7) {
            const int r0 = w * 16 + lg;
            const uint32_t* qa = smu + r0 * SQS + lt;
            const uint32_t* qb = qa + 8 * SQS;
            const uint32_t* bp = smu + K1_SW + lt * SWS + lg;
            #pragma unroll 4
            for (int kt = 0; kt < 16; ++kt) {
                const int kc = kt * 8;
                uint4 a;
                a.x = qa[kc]; a.y = qb[kc]; a.z = qa[kc + 4]; a.w = qb[kc + 4];
                const uint32_t* bk = bp + kc * SWS;
                #pragma unroll
                for (int t = 0; t < 13; ++t) {
                    uint2 bb;
                    bb.x = bk[t * 8];
                    bb.y = bk[4 * SWS + t * 8];
                    mma8(dA[t], a, bb);
                }
            }
        }
    }
    __syncthreads();   // all MMA smem reads done; sQ region becomes dyBuf

    // epilogue: dy = D + bias (tf32-rounded) -> dyBuf [100][108]
    if (w < 7) {
        const int r0 = w * 16 + lg;
        #pragma unroll
        for (int t = 0; t < 13; ++t) {
            const int j0 = t * 8 + 2 * lt;
            const float b0 = sm[K1_BIAS + j0], b1 = sm[K1_BIAS + j0 + 1];
            if (r0 < NROW)
                *(float2*)(sm + r0 * DYS + j0) =
                    make_float2(tf32f(dA[t][0] + b0), tf32f(dA[t][1] + b1));
            if (r0 + 8 < NROW)
                *(float2*)(sm + (r0 + 8) * DYS + j0) =
                    make_float2(tf32f(dA[t][2] + b0), tf32f(dA[t][3] + b1));
        }
    }
    __syncthreads();

    // writeout: pw[b][n][m] = dy[n][3+m] (n<100, m<100; else 0), dw[b][n][k]
    float* pwb = g_pw + (size_t)b * 10816;
    for (int idx = tid; idx < 104 * 26; idx += 256) {
        const int n = idx / 26;
        const int m4 = (idx - n * 26) * 4;
        float4 o;
        o.x = (n < NROW && m4 + 0 < NROW) ? sm[n * DYS + 3 + m4 + 0] : 0.0f;
        o.y = (n < NROW && m4 + 1 < NROW) ? sm[n * DYS + 3 + m4 + 1] : 0.0f;
        o.z = (n < NROW && m4 + 2 < NROW) ? sm[n * DYS + 3 + m4 + 2] : 0.0f;
        o.w = (n < NROW && m4 + 3 < NROW) ? sm[n * DYS + 3 + m4 + 3] : 0.0f;
        *(float4*)(pwb + n * 104 + m4) = o;
    }
    if (tid < NROW) {
        float4 d;
        d.x = sm[tid * DYS + 0];
        d.y = sm[tid * DYS + 1];
        d.z = sm[tid * DYS + 2];
        d.w = 0.0f;
        *(float4*)(g_dw + b * 400 + tid * 4) = d;
    }
}

// ================= K3: out = pw @ depth, fused conv + LN =================
// smem: DP [104][264]=27456f (stride 264, mod32=8) | dwS 400f @27456
//       MU 112f @27856 | INV 112f @27968 ; total 28080f = 112,320B -> occ 2
#define DPS   264
#define K3_DW 27456
#define K3_MU 27856
#define K3_IV 27968
#define K3_F  28080

__global__ void __launch_bounds__(256, 2)
k3_gemm(const float* __restrict__ value, const float* __restrict__ gamma,
        const float* __restrict__ beta,  float* __restrict__ out)
{
    extern __shared__ float sm[];
    const uint32_t* smu = (const uint32_t*)sm;
    const int b = blockIdx.x, tid = threadIdx.x;
    const int w = tid >> 5, lane = tid & 31;
    const int lg = lane >> 2, lt = lane & 3;
    const float* vg = value + (size_t)b * (NROW * CDIM);
    float*       og = out   + (size_t)b * (NROW * CDIM);

    // stage dw
    for (int idx = tid; idx < 400; idx += 256)
        sm[K3_DW + idx] = g_dw[b * 400 + idx];
    __syncthreads();

    // conv: depth[m][c] = relu(dw0*v[c-1] + dw1*v[c] + dw2*v[c+1]) (tf32)
    for (int idx = tid; idx < NROW * 64; idx += 256) {
        const int m = idx >> 6;
        const int c4 = (idx & 63) << 2;
        const float* vr = vg + m * CDIM;
        const float d0 = sm[K3_DW + m * 4 + 0];
        const float d1 = sm[K3_DW + m * 4 + 1];
        const float d2 = sm[K3_DW + m * 4 + 2];
        const float4 vc = *(const float4*)(vr + c4);
        const float vl  = (c4 == 0)   ? 0.0f : vr[c4 - 1];
        const float vrt = (c4 == 252) ? 0.0f : vr[c4 + 4];
        uint4 u;
        u.x = tf32c(fmaxf(fmaf(d0, vl,   fmaf(d1, vc.x, d2 * vc.y)), 0.0f));
        u.y = tf32c(fmaxf(fmaf(d0, vc.x, fmaf(d1, vc.y, d2 * vc.z)), 0.0f));
        u.z = tf32c(fmaxf(fmaf(d0, vc.y, fmaf(d1, vc.z, d2 * vc.w)), 0.0f));
        u.w = tf32c(fmaxf(fmaf(d0, vc.z, fmaf(d1, vc.w, d2 * vrt)), 0.0f));
        *(uint4*)(sm + m * DPS + c4) = u;
    }
    for (int idx = tid; idx < 4 * 64; idx += 256) {   // zero K-pad rows m=100..103
        const int m = NROW + (idx >> 6);
        const int c4 = (idx & 63) << 2;
        *(uint4*)(sm + m * DPS + c4) = make_uint4(0u, 0u, 0u, 0u);
    }
    __syncthreads();

    // MMA: warp w (<7) owns m-tile w (rows r0, r0+8); loops nb 0..3 over 64-col blocks.
    if (w < 7) {
        const int r0 = w * 16 + lg;
        const float* pwb = g_pw + (size_t)b * 10816;
        // preload all 13 A-fragments from pw scratch (L2; 52 independent LDGs)
        uint4 af[13];
        #pragma unroll
        for (int kt = 0; kt < 13; ++kt) {
            const int kc = kt * 8;
            af[kt].x = __float_as_uint(pwb[r0 * 104 + kc + lt]);
            af[kt].y = __float_as_uint(pwb[(r0 + 8) * 104 + kc + lt]);
            af[kt].z = __float_as_uint(pwb[r0 * 104 + kc + lt + 4]);
            af[kt].w = __float_as_uint(pwb[(r0 + 8) * 104 + kc + lt + 4]);
        }
        float s0 = 0.0f, q0 = 0.0f, s1 = 0.0f, q1 = 0.0f;
        #pragma unroll 1
        for (int nb = 0; nb < 4; ++nb) {
            float dC[8][4];
            #pragma unroll
            for (int t = 0; t < 8; ++t)
                #pragma unroll
                for (int r = 0; r < 4; ++r) dC[t][r] = 0.0f;
            const uint32_t* dp = smu + lt * DPS + nb * 64 + lg;
            #pragma unroll
            for (int kt = 0; kt < 13; ++kt) {
                const uint32_t* dk = dp + kt * 8 * DPS;
                #pragma unroll
                for (int t = 0; t < 8; ++t) {
                    uint2 bb;
                    bb.x = dk[t * 8];
                    bb.y = dk[4 * DPS + t * 8];
                    mma8(dC[t], af[kt], bb);
                }
            }
            // raw store + LN partials
            #pragma unroll
            for (int t = 0; t < 8; ++t) {
                const int j0 = nb * 64 + t * 8 + 2 * lt;
                if (r0 < NROW)
                    *(float2*)(og + r0 * CDIM + j0) = make_float2(dC[t][0], dC[t][1]);
                if (r0 + 8 < NROW)
                    *(float2*)(og + (r0 + 8) * CDIM + j0) = make_float2(dC[t][2], dC[t][3]);
                s0 += dC[t][0] + dC[t][1];
                q0 = fmaf(dC[t][0], dC[t][0], fmaf(dC[t][1], dC[t][1], q0));
                s1 += dC[t][2] + dC[t][3];
                q1 = fmaf(dC[t][2], dC[t][2], fmaf(dC[t][3], dC[t][3], q1));
            }
        }
        // reduce over lt and publish mu/inv
        s0 += __shfl_xor_sync(~0u, s0, 1); s0 += __shfl_xor_sync(~0u, s0, 2);
        q0 += __shfl_xor_sync(~0u, q0, 1); q0 += __shfl_xor_sync(~0u, q0, 2);
        s1 += __shfl_xor_sync(~0u, s1, 1); s1 += __shfl_xor_sync(~0u, s1, 2);
        q1 += __shfl_xor_sync(~0u, q1, 1); q1 += __shfl_xor_sync(~0u, q1, 2);
        if (lt == 0) {
            if (r0 < NROW) {
                const float mu = s0 * (1.0f / 256.0f);
                float var = fmaf(-mu, mu, q0 * (1.0f / 256.0f));
                var = fmaxf(var, 0.0f);
                sm[K3_MU + r0] = mu;
                sm[K3_IV + r0] = rsqrtf(var + 1e-5f);
            }
            if (r0 + 8 < NROW) {
                const float mu = s1 * (1.0f / 256.0f);
                float var = fmaf(-mu, mu, q1 * (1.0f / 256.0f));
                var = fmaxf(var, 0.0f);
                sm[K3_MU + r0 + 8] = mu;
                sm[K3_IV + r0 + 8] = rsqrtf(var + 1e-5f);
            }
        }
    }
    __syncthreads();

    // in-place normalize (reads raw out from L2)
    for (int idx = tid; idx < NROW * 64; idx += 256) {
        const int n = idx >> 6;
        const int c4 = (idx & 63) << 2;
        float4 v = *(const float4*)(og + n * CDIM + c4);
        const float mu  = sm[K3_MU + n];
        const float inv = sm[K3_IV + n];
        const float4 g  = *(const float4*)(gamma + c4);
        const float4 bt = *(const float4*)(beta + c4);
        v.x = fmaf((v.x - mu) * inv, g.x, bt.x);
        v.y = fmaf((v.y - mu) * inv, g.y, bt.y);
        v.z = fmaf((v.z - mu) * inv, g.z, bt.z);
        v.w = fmaf((v.w - mu) * inv, g.w, bt.w);
        *(float4*)(og + n * CDIM + c4) = v;
    }
}

extern "C" void kernel_launch(void* const* d_in, const int* in_sizes, int n_in,
                              void* d_out, int out_size)
{
    const float* query = (const float*)d_in[0];
    const float* value = (const float*)d_in[1];
    const float* Wwl   = (const float*)d_in[2];
    const float* bwl   = (const float*)d_in[3];
    const float* gamma = (const float*)d_in[4];
    const float* beta  = (const float*)d_in[5];
    float* out = (float*)d_out;

    const int B = in_sizes[0] / (NROW * CDIM);   // 512
    cudaFuncSetAttribute(k1_gemm, cudaFuncAttributeMaxDynamicSharedMemorySize,
                         K1_F * (int)sizeof(float));
    cudaFuncSetAttribute(k3_gemm, cudaFuncAttributeMaxDynamicSharedMemorySize,
                         K3_F * (int)sizeof(float));
    k1_gemm<<<B, 256, K1_F * sizeof(float)>>>(query, Wwl, bwl);
    k3_gemm<<<B, 256, K3_F * sizeof(float)>>>(value, gamma, beta, out);
}